// round 5
// baseline (speedup 1.0000x reference)
#include <cuda_runtime.h>

#define BQ 16      // batch
#define NH 32      // heads
#define HD 128     // head dim
#define LL 4096    // seq len
#define CC 1536    // q_lora_rank
#define NW 8       // warps per attention CTA
#define SPLIT 4    // L-splits per (b,h)
#define NTASK (BQ * NH * SPLIT)   // 2048
#define PCTAS 296  // persistent CTAs (2 per SM)
#define C4 (CC / 4)   // 384 float4 per row
#define RPW 4      // qproj rows per warp

// Scratch for projected q: [B, H, HD] = 256 KB.
__device__ float g_q[BQ * NH * HD];
// Partial softmax results: indexed by bhs = (b*NH+h)*SPLIT + s.
__device__ float g_pm[BQ * NH * SPLIT];
__device__ float g_ps[BQ * NH * SPLIT];
__device__ float g_pa[BQ * NH * SPLIT * HD];

// ---------------------------------------------------------------------------
// Kernel 1: q = hidden @ w_q^T + b_q      (4096 x 1536 x 16 skinny GEMM)
// 256 CTAs x 128 threads; warp owns 4 rows x all 16 batches. Lane indexes the
// contraction so every w_q load is a coalesced 512B LDG.128; 16 independent
// w-loads issued back-to-back per chunk to cover DRAM latency. hidden is
// L1-resident. Cross-lane reduction via padded smem transpose. ~6 us.
// ---------------------------------------------------------------------------
__global__ void __launch_bounds__(128, 2) qproj_kernel(const float* __restrict__ hidden,
                                                       const float* __restrict__ wq,
                                                       const float* __restrict__ bq) {
    const int warp = threadIdx.x >> 5;
    const int lane = threadIdx.x & 31;
    const int gw   = blockIdx.x * 4 + warp;   // 0..1023
    const int row0 = gw * RPW;

    const float4* w4 = reinterpret_cast<const float4*>(wq);
    const float4* h4 = reinterpret_cast<const float4*>(hidden);

    float acc[RPW][BQ];
    #pragma unroll
    for (int r = 0; r < RPW; r++)
        #pragma unroll
        for (int b = 0; b < BQ; b++) acc[r][b] = 0.0f;

    #pragma unroll
    for (int chunk = 0; chunk < 3; chunk++) {     // 3 chunks x 4 steps = 384 c4
        float4 wv[4][RPW];
        #pragma unroll
        for (int st = 0; st < 4; st++)
            #pragma unroll
            for (int r = 0; r < RPW; r++)
                wv[st][r] = w4[(size_t)(row0 + r) * C4 + chunk * 128 + st * 32 + lane];

        #pragma unroll
        for (int st = 0; st < 4; st++) {
            const int c4 = chunk * 128 + st * 32 + lane;
            #pragma unroll
            for (int b = 0; b < BQ; b++) {
                float4 hv = h4[b * C4 + c4];
                #pragma unroll
                for (int r = 0; r < RPW; r++) {
                    acc[r][b] = fmaf(wv[st][r].x, hv.x,
                                fmaf(wv[st][r].y, hv.y,
                                fmaf(wv[st][r].z, hv.z,
                                fmaf(wv[st][r].w, hv.w, acc[r][b]))));
                }
            }
        }
    }

    __shared__ float red[4][32][65];
    #pragma unroll
    for (int r = 0; r < RPW; r++)
        #pragma unroll
        for (int b = 0; b < BQ; b++)
            red[warp][lane][r * BQ + b] = acc[r][b];
    __syncwarp();

    #pragma unroll
    for (int half = 0; half < 2; half++) {
        const int p = lane + half * 32;
        float s0 = 0.f, s1 = 0.f, s2 = 0.f, s3 = 0.f;
        #pragma unroll
        for (int j = 0; j < 32; j += 4) {
            s0 += red[warp][j + 0][p];
            s1 += red[warp][j + 1][p];
            s2 += red[warp][j + 2][p];
            s3 += red[warp][j + 3][p];
        }
        const int r   = p >> 4;
        const int b   = p & 15;
        const int row = row0 + r;
        g_q[b * (NH * HD) + row] = (s0 + s1) + (s2 + s3) + bq[row];
    }
}

// ---------------------------------------------------------------------------
// Kernel 2: PERSISTENT partial attention. 296 CTAs; CTA strides over the
// 2048 (bh, quarter-L) tasks (static, deterministic). Per task: 8 warps
// stream 128 l's each (plain LDG.128, no .cs), online softmax, intra-CTA
// merge, write unnormalized (M, den, num[128]) partials. No fences/atomics.
// ---------------------------------------------------------------------------
__global__ void __launch_bounds__(NW * 32) attn_kernel(const float* __restrict__ Kd,
                                                       const float* __restrict__ Vd) {
    const int warp = threadIdx.x >> 5;
    const int lane = threadIdx.x & 31;

    const int S4  = NH * HD / 4;          // float4 stride between l's = 1024
    const int LPC = LL / SPLIT;           // 1024 l per task
    const int LPW = LPC / NW;             // 128 l per warp

    __shared__ float  sm_m[NW];
    __shared__ float  sm_s[NW];
    __shared__ float4 sm_acc[NW][32];

    for (int t = blockIdx.x; t < NTASK; t += PCTAS) {
        const int s  = t & (SPLIT - 1);
        const int bh = t >> 2;            // b*NH + h
        const int b  = bh >> 5;
        const int h  = bh & 31;

        const float4 qv = *reinterpret_cast<const float4*>(g_q + (size_t)bh * HD + 4 * lane);

        const int l0 = s * LPC + warp * LPW;
        const size_t base4 = (((size_t)b * LL) * NH + h) * (HD / 4);
        const float4* kp = reinterpret_cast<const float4*>(Kd) + base4 + (size_t)l0 * S4 + lane;
        const float4* vp = reinterpret_cast<const float4*>(Vd) + base4 + (size_t)l0 * S4 + lane;

        float m = -1e30f;
        float sden = 0.0f;
        float ax = 0.f, ay = 0.f, az = 0.f, aw = 0.f;

        #pragma unroll 1
        for (int i = 0; i < LPW; i += 4) {
            float4 kv[4], vv[4];
            #pragma unroll
            for (int u = 0; u < 4; u++) {
                kv[u] = kp[(size_t)u * S4];
                vv[u] = vp[(size_t)u * S4];
            }
            kp += 4 * S4;
            vp += 4 * S4;

            #pragma unroll
            for (int u = 0; u < 4; u++) {
                float x = kv[u].x * qv.x + kv[u].y * qv.y + kv[u].z * qv.z + kv[u].w * qv.w;
                x += __shfl_xor_sync(0xffffffffu, x, 16);
                x += __shfl_xor_sync(0xffffffffu, x, 8);
                x += __shfl_xor_sync(0xffffffffu, x, 4);
                x += __shfl_xor_sync(0xffffffffu, x, 2);
                x += __shfl_xor_sync(0xffffffffu, x, 1);

                if (x > m) {              // warp-uniform, rare
                    float sc = __expf(m - x);
                    sden *= sc; ax *= sc; ay *= sc; az *= sc; aw *= sc;
                    m = x;
                }
                float p = __expf(x - m);
                sden += p;
                ax += p * vv[u].x;
                ay += p * vv[u].y;
                az += p * vv[u].z;
                aw += p * vv[u].w;
            }
        }

        if (lane == 0) { sm_m[warp] = m; sm_s[warp] = sden; }
        sm_acc[warp][lane] = make_float4(ax, ay, az, aw);
        __syncthreads();

        if (threadIdx.x < HD) {
            const int k = threadIdx.x;
            float M = sm_m[0];
            #pragma unroll
            for (int w = 1; w < NW; w++) M = fmaxf(M, sm_m[w]);
            float den = 0.0f, num = 0.0f;
            #pragma unroll
            for (int w = 0; w < NW; w++) {
                float e = __expf(sm_m[w] - M);
                den += e * sm_s[w];
                num += e * reinterpret_cast<const float*>(&sm_acc[w][0])[k];
            }
            g_pa[(size_t)t * HD + k] = num;
            if (k == 0) { g_pm[t] = M; g_ps[t] = den; }
        }
        __syncthreads();                  // smem reuse across tasks
    }
}

// ---------------------------------------------------------------------------
// Kernel 3: combine SPLIT partials per (b,h) and write output. ~2 us.
// ---------------------------------------------------------------------------
__global__ void __launch_bounds__(HD) combine_kernel(float* __restrict__ out) {
    const int bh = blockIdx.x;
    const int k  = threadIdx.x;

    float M = g_pm[bh * SPLIT];
    #pragma unroll
    for (int s = 1; s < SPLIT; s++) M = fmaxf(M, g_pm[bh * SPLIT + s]);

    float den = 0.0f, num = 0.0f;
    #pragma unroll
    for (int s = 0; s < SPLIT; s++) {
        float e = __expf(g_pm[bh * SPLIT + s] - M);
        den += e * g_ps[bh * SPLIT + s];
        num += e * g_pa[(size_t)(bh * SPLIT + s) * HD + k];
    }
    out[(size_t)bh * HD + k] = num / den;
}

// ---------------------------------------------------------------------------
// Inputs (metadata order): 0 hidden_states_q [B,1536] f32
//                          1 key_states      [B,L,H,HD] f32
//                          2 value_states    [B,L,H,HD] f32
//                          3 w_q             [H*HD,1536] f32
//                          4 b_q             [H*HD] f32
// Output: [B, H*HD] f32
// ---------------------------------------------------------------------------
extern "C" void kernel_launch(void* const* d_in, const int* in_sizes, int n_in,
                              void* d_out, int out_size) {
    (void)in_sizes; (void)n_in; (void)out_size;
    const float* hidden = (const float*)d_in[0];
    const float* Kd     = (const float*)d_in[1];
    const float* Vd     = (const float*)d_in[2];
    const float* wq     = (const float*)d_in[3];
    const float* bq     = (const float*)d_in[4];
    float* out          = (float*)d_out;

    qproj_kernel<<<(NH * HD) / (RPW * 4), 128>>>(hidden, wq, bq);
    attn_kernel<<<PCTAS, NW * 32>>>(Kd, Vd);
    combine_kernel<<<BQ * NH, HD>>>(out);
}

// round 6
// speedup vs baseline: 1.0437x; 1.0437x over previous
#include <cuda_runtime.h>

#define BQ 16      // batch
#define NH 32      // heads
#define HD 128     // head dim
#define LL 4096    // seq len
#define CC 1536    // q_lora_rank
#define NW 8       // warps per attention CTA
#define C4 (CC / 4)   // 384 float4 per row
#define RPW 4      // qproj rows per warp

// Scratch for projected q: [B, H, HD] = 256 KB.
__device__ float g_q[BQ * NH * HD];

// ---------------------------------------------------------------------------
// Kernel 1: q = hidden @ w_q^T + b_q      (4096 x 1536 x 16 skinny GEMM)
// 256 CTAs x 128 threads; warp owns 4 rows x all 16 batches. Lane indexes the
// contraction so every w_q load is a coalesced 512B LDG.128; 16 independent
// w-loads issued back-to-back per chunk. In steady-state graph replay w_q is
// L2-resident (25 MB in 126 MB L2) -> ~6 us.
// ---------------------------------------------------------------------------
__global__ void __launch_bounds__(128, 2) qproj_kernel(const float* __restrict__ hidden,
                                                       const float* __restrict__ wq,
                                                       const float* __restrict__ bq) {
    const int warp = threadIdx.x >> 5;
    const int lane = threadIdx.x & 31;
    const int gw   = blockIdx.x * 4 + warp;   // 0..1023
    const int row0 = gw * RPW;

    const float4* w4 = reinterpret_cast<const float4*>(wq);
    const float4* h4 = reinterpret_cast<const float4*>(hidden);

    float acc[RPW][BQ];
    #pragma unroll
    for (int r = 0; r < RPW; r++)
        #pragma unroll
        for (int b = 0; b < BQ; b++) acc[r][b] = 0.0f;

    #pragma unroll
    for (int chunk = 0; chunk < 3; chunk++) {     // 3 chunks x 4 steps = 384 c4
        float4 wv[4][RPW];
        #pragma unroll
        for (int st = 0; st < 4; st++)
            #pragma unroll
            for (int r = 0; r < RPW; r++)
                wv[st][r] = w4[(size_t)(row0 + r) * C4 + chunk * 128 + st * 32 + lane];

        #pragma unroll
        for (int st = 0; st < 4; st++) {
            const int c4 = chunk * 128 + st * 32 + lane;
            #pragma unroll
            for (int b = 0; b < BQ; b++) {
                float4 hv = h4[b * C4 + c4];
                #pragma unroll
                for (int r = 0; r < RPW; r++) {
                    acc[r][b] = fmaf(wv[st][r].x, hv.x,
                                fmaf(wv[st][r].y, hv.y,
                                fmaf(wv[st][r].z, hv.z,
                                fmaf(wv[st][r].w, hv.w, acc[r][b]))));
                }
            }
        }
    }

    __shared__ float red[4][32][65];
    #pragma unroll
    for (int r = 0; r < RPW; r++)
        #pragma unroll
        for (int b = 0; b < BQ; b++)
            red[warp][lane][r * BQ + b] = acc[r][b];
    __syncwarp();

    #pragma unroll
    for (int half = 0; half < 2; half++) {
        const int p = lane + half * 32;
        float s0 = 0.f, s1 = 0.f, s2 = 0.f, s3 = 0.f;
        #pragma unroll
        for (int j = 0; j < 32; j += 4) {
            s0 += red[warp][j + 0][p];
            s1 += red[warp][j + 1][p];
            s2 += red[warp][j + 2][p];
            s3 += red[warp][j + 3][p];
        }
        const int r   = p >> 4;
        const int b   = p & 15;
        const int row = row0 + r;
        g_q[b * (NH * HD) + row] = (s0 + s1) + (s2 + s3) + bq[row];
    }
}

// ---------------------------------------------------------------------------
// Kernel 2: fused single-pass attention (R1 structure: one CTA per (b,h),
// 512 CTAs, 8 warps x 512 l) with SOFTWARE DOUBLE BUFFERING: group B's 8
// LDG.128 are issued before group A's dependent SHFL/exp chain, so loads
// stay continuously in flight instead of only during a burst window.
// Buffers are statically indexed (no dynamic array indexing -> no spills).
// ---------------------------------------------------------------------------
__device__ __forceinline__ void attn_group(const float4* kv, const float4* vv,
                                           const float4& qv, float& m, float& sden,
                                           float& ax, float& ay, float& az, float& aw) {
    #pragma unroll
    for (int u = 0; u < 4; u++) {
        float x = kv[u].x * qv.x + kv[u].y * qv.y + kv[u].z * qv.z + kv[u].w * qv.w;
        x += __shfl_xor_sync(0xffffffffu, x, 16);
        x += __shfl_xor_sync(0xffffffffu, x, 8);
        x += __shfl_xor_sync(0xffffffffu, x, 4);
        x += __shfl_xor_sync(0xffffffffu, x, 2);
        x += __shfl_xor_sync(0xffffffffu, x, 1);

        if (x > m) {                      // warp-uniform, rare
            float sc = __expf(m - x);
            sden *= sc; ax *= sc; ay *= sc; az *= sc; aw *= sc;
            m = x;
        }
        float p = __expf(x - m);
        sden += p;
        ax += p * vv[u].x;
        ay += p * vv[u].y;
        az += p * vv[u].z;
        aw += p * vv[u].w;
    }
}

__global__ void __launch_bounds__(NW * 32) attn_kernel(const float* __restrict__ Kd,
                                                       const float* __restrict__ Vd,
                                                       float* __restrict__ out) {
    const int bh   = blockIdx.x;          // b*NH + h
    const int b    = bh >> 5;
    const int h    = bh & 31;
    const int warp = threadIdx.x >> 5;
    const int lane = threadIdx.x & 31;

    const float4 qv = *reinterpret_cast<const float4*>(g_q + (size_t)bh * HD + 4 * lane);

    const int S4  = NH * HD / 4;          // float4 stride between l's = 1024
    const int LPW = LL / NW;              // 512 l per warp
    const size_t base4 = (((size_t)b * LL) * NH + h) * (HD / 4);

    const float4* kp = reinterpret_cast<const float4*>(Kd) + base4
                       + (size_t)(warp * LPW) * S4 + lane;
    const float4* vp = reinterpret_cast<const float4*>(Vd) + base4
                       + (size_t)(warp * LPW) * S4 + lane;

    float m = -1e30f;
    float sden = 0.0f;
    float ax = 0.f, ay = 0.f, az = 0.f, aw = 0.f;

    float4 kA[4], vA[4], kB[4], vB[4];

    // Prologue: fill buffer A.
    #pragma unroll
    for (int u = 0; u < 4; u++) { kA[u] = kp[(size_t)u * S4]; vA[u] = vp[(size_t)u * S4]; }
    kp += 4 * S4; vp += 4 * S4;

    // 512 l = 128 groups of 4 = 64 A/B pairs. Steady state: load next buffer,
    // then compute current one.
    #pragma unroll 1
    for (int i = 0; i < LPW / 8 - 1; i++) {
        #pragma unroll
        for (int u = 0; u < 4; u++) { kB[u] = kp[(size_t)u * S4]; vB[u] = vp[(size_t)u * S4]; }
        kp += 4 * S4; vp += 4 * S4;
        attn_group(kA, vA, qv, m, sden, ax, ay, az, aw);

        #pragma unroll
        for (int u = 0; u < 4; u++) { kA[u] = kp[(size_t)u * S4]; vA[u] = vp[(size_t)u * S4]; }
        kp += 4 * S4; vp += 4 * S4;
        attn_group(kB, vB, qv, m, sden, ax, ay, az, aw);
    }
    // Epilogue pair.
    #pragma unroll
    for (int u = 0; u < 4; u++) { kB[u] = kp[(size_t)u * S4]; vB[u] = vp[(size_t)u * S4]; }
    attn_group(kA, vA, qv, m, sden, ax, ay, az, aw);
    attn_group(kB, vB, qv, m, sden, ax, ay, az, aw);

    // Cross-warp merge.
    __shared__ float  sm_m[NW];
    __shared__ float  sm_s[NW];
    __shared__ float4 sm_acc[NW][32];

    if (lane == 0) { sm_m[warp] = m; sm_s[warp] = sden; }
    sm_acc[warp][lane] = make_float4(ax, ay, az, aw);
    __syncthreads();

    if (threadIdx.x < HD) {
        const int k = threadIdx.x;
        float M = sm_m[0];
        #pragma unroll
        for (int w = 1; w < NW; w++) M = fmaxf(M, sm_m[w]);
        float den = 0.0f, num = 0.0f;
        #pragma unroll
        for (int w = 0; w < NW; w++) {
            float e = __expf(sm_m[w] - M);
            den += e * sm_s[w];
            num += e * reinterpret_cast<const float*>(&sm_acc[w][0])[k];
        }
        out[(size_t)bh * HD + k] = num / den;
    }
}

// ---------------------------------------------------------------------------
// Inputs (metadata order): 0 hidden_states_q [B,1536] f32
//                          1 key_states      [B,L,H,HD] f32
//                          2 value_states    [B,L,H,HD] f32
//                          3 w_q             [H*HD,1536] f32
//                          4 b_q             [H*HD] f32
// Output: [B, H*HD] f32
// ---------------------------------------------------------------------------
extern "C" void kernel_launch(void* const* d_in, const int* in_sizes, int n_in,
                              void* d_out, int out_size) {
    (void)in_sizes; (void)n_in; (void)out_size;
    const float* hidden = (const float*)d_in[0];
    const float* Kd     = (const float*)d_in[1];
    const float* Vd     = (const float*)d_in[2];
    const float* wq     = (const float*)d_in[3];
    const float* bq     = (const float*)d_in[4];
    float* out          = (float*)d_out;

    qproj_kernel<<<(NH * HD) / (RPW * 4), 128>>>(hidden, wq, bq);
    attn_kernel<<<BQ * NH, NW * 32>>>(Kd, Vd, out);
}